// round 10
// baseline (speedup 1.0000x reference)
#include <cuda_runtime.h>
#include <cuda_bf16.h>

#define BATCH   2
#define NPTS    6144
#define DIM     32
#define RADIUS2 0.0009f      // 0.03^2
#define SIM_T   0.7f
#define EPS_N   1e-8f
#define FULLMASK 0xffffffffu

#define GRID1   10           // cells per axis
#define NCELLS  1000
#define INV_CELL 33.0f       // cell width = 1/33 = 0.0303 > radius (robust margin)

#define HL_CAP  96           // per-warp hit list (expected hits ~13)
#define MT      512          // main kernel threads
#define MWPB    (MT / 32)    // 16 warps per block

// -------- scratch (__device__ globals; no allocation allowed) --------
__device__ float4 g_q[BATCH * NPTS];            // (x,y,z,|p|^2) per point
__device__ float  g_norm[BATCH * NPTS];         // max(||emb||, eps)
__device__ int    g_cell[BATCH * NPTS];         // cell id if leaf, -1 if not
__device__ int    g_hist[BATCH * NCELLS];       // zero-init; re-zeroed by main
__device__ int    g_cur[BATCH * NCELLS];        // scatter cursors (set by scan)
__device__ float4 g_bq[BATCH * NPTS];           // binned leaf points
__device__ unsigned short g_bidx[BATCH * NPTS]; // binned -> original local idx
__device__ int    g_cellstart[BATCH * (NCELLS + 1)];
__device__ int    g_leaf_cnt[BATCH];

__device__ __forceinline__ int cell_of(float x, float y, float z) {
    int cx = (int)floorf(x * INV_CELL);
    int cy = (int)floorf(y * INV_CELL);
    int cz = (int)floorf(z * INV_CELL);
    cx = min(max(cx, 0), GRID1 - 1);
    cy = min(max(cy, 0), GRID1 - 1);
    cz = min(max(cz, 0), GRID1 - 1);
    return (cx * GRID1 + cy) * GRID1 + cz;
}

// ---------------------------------------------------------------------------
// Kernel 1: prep (role-split).
//   copy role : 4 independent float4s per thread  (out = emb)
//   point role: 1 point per thread -> norm, g_q, g_cell, histogram atomics
// ---------------------------------------------------------------------------
#define NP        (BATCH * NPTS)                 // 12288 points
#define COPY_THR  (NP * 8 / 4)                   // 24576 copy threads
#define PREP_THR  (COPY_THR + NP)

__global__ __launch_bounds__(256) void prep_kernel(
    const float* __restrict__ points,
    const float* __restrict__ emb,
    const int*   __restrict__ leaf_mask,
    float*       __restrict__ out)
{
    int tid = blockIdx.x * blockDim.x + threadIdx.x;
    if (tid < COPY_THR) {
        const float4* src = (const float4*)emb;
        float4*       dst = (float4*)out;
        int base = tid * 4;
        float4 v0 = src[base + 0];
        float4 v1 = src[base + 1];
        float4 v2 = src[base + 2];
        float4 v3 = src[base + 3];
        dst[base + 0] = v0;
        dst[base + 1] = v1;
        dst[base + 2] = v2;
        dst[base + 3] = v3;
        return;
    }
    int p = tid - COPY_THR;
    if (p >= NP) return;

    const float4* e4 = (const float4*)(emb) + p * 8;
    float s = 0.0f;
    #pragma unroll
    for (int k = 0; k < 8; k++) {
        float4 v = e4[k];
        s += __fmaf_rn(v.w, v.w,
             __fmaf_rn(v.z, v.z,
             __fmaf_rn(v.y, v.y, __fmul_rn(v.x, v.x))));
    }
    g_norm[p] = fmaxf(sqrtf(s), EPS_N);

    float x = points[p * 3 + 0];
    float y = points[p * 3 + 1];
    float z = points[p * 3 + 2];
    float pn = __fadd_rn(__fadd_rn(__fmul_rn(x, x), __fmul_rn(y, y)),
                         __fmul_rn(z, z));
    g_q[p] = make_float4(x, y, z, pn);

    int b = p / NPTS;
    if (leaf_mask[p] > 0) {
        int c = cell_of(x, y, z);
        g_cell[p] = c;
        atomicAdd(&g_hist[b * NCELLS + c], 1);
    } else {
        g_cell[p] = -1;
    }
}

// ---------------------------------------------------------------------------
// Kernel 2: scan histogram -> cellstart + cursors + leaf_cnt. One block/batch.
// ---------------------------------------------------------------------------
__global__ __launch_bounds__(1024) void scan_kernel()
{
    int b = blockIdx.x;
    int t = threadIdx.x;
    __shared__ int sc[1024];

    int h = (t < NCELLS) ? g_hist[b * NCELLS + t] : 0;
    sc[t] = h;
    __syncthreads();
    for (int d = 1; d < 1024; d <<= 1) {
        int v = (t >= d) ? sc[t - d] : 0;
        __syncthreads();
        sc[t] += v;
        __syncthreads();
    }
    if (t < NCELLS) {
        int start = sc[t] - h;                   // exclusive prefix
        g_cellstart[b * (NCELLS + 1) + t] = start;
        g_cur[b * NCELLS + t] = start;
    }
    if (t == NCELLS - 1) {
        g_cellstart[b * (NCELLS + 1) + NCELLS] = sc[t];
        g_leaf_cnt[b] = sc[t];
    }
}

// ---------------------------------------------------------------------------
// Kernel 3: parallel scatter. One thread per point.
// (Within-cell order nondeterministic; fixed by hit-list sort in main.)
// ---------------------------------------------------------------------------
__global__ __launch_bounds__(256) void scatter_kernel()
{
    int p = blockIdx.x * blockDim.x + threadIdx.x;
    if (p >= NP) return;
    int c = g_cell[p];
    if (c < 0) return;
    int b = p / NPTS;
    int slot = atomicAdd(&g_cur[b * NCELLS + c], 1);
    g_bq[b * NPTS + slot]   = g_q[p];
    g_bidx[b * NPTS + slot] = (unsigned short)(p - b * NPTS);
}

// ---------------------------------------------------------------------------
// Kernel 4: main. One warp per binned leaf query. Also re-zeroes g_hist for
// the next graph replay (block (0,0), before any early exit).
// ---------------------------------------------------------------------------
__global__ __launch_bounds__(MT) void main_kernel(
    const float* __restrict__ emb,
    const float* __restrict__ W1,
    const float* __restrict__ b1,
    const float* __restrict__ W2,
    const float* __restrict__ b2,
    float*       __restrict__ out)
{
    __shared__ float sW1[64 * 32];
    __shared__ float sW2[32 * 32];
    __shared__ float sb1[32], sb2[32];
    __shared__ unsigned short hl[MWPB * HL_CAP];

    // re-zero histogram for next replay (hist already consumed by scan)
    if (blockIdx.x == 0 && blockIdx.y == 0) {
        for (int k = threadIdx.x; k < BATCH * NCELLS; k += MT) g_hist[k] = 0;
    }

    int b   = blockIdx.y;
    int cnt = g_leaf_cnt[b];
    if (cnt < 10) return;                        // batch early-exit (uniform)
    int warp0 = blockIdx.x * MWPB;
    if (warp0 >= cnt) return;                    // dead block (uniform)

    // stage MLP weights (live blocks only)
    for (int k = threadIdx.x; k < 64 * 32; k += MT) sW1[k] = W1[k];
    for (int k = threadIdx.x; k < 32 * 32; k += MT) sW2[k] = W2[k];
    if (threadIdx.x < 32) { sb1[threadIdx.x] = b1[threadIdx.x];
                            sb2[threadIdx.x] = b2[threadIdx.x]; }
    __syncthreads();

    int wid  = threadIdx.x >> 5;
    int lane = threadIdx.x & 31;
    int w    = warp0 + wid;
    if (w >= cnt) return;

    int sb_ = b * NPTS;
    float4 qi = g_bq[sb_ + w];
    int    i  = g_bidx[sb_ + w];
    int    gi = sb_ + i;

    float ni = g_norm[gi];
    float ei = emb[gi * DIM + lane];

    const float* embb  = emb    + sb_ * DIM;
    const float* normb = g_norm + sb_;
    const int*   cs    = g_cellstart + b * (NCELLS + 1);
    unsigned short* myhl = hl + wid * HL_CAP;

    int cx = min(max((int)floorf(qi.x * INV_CELL), 0), GRID1 - 1);
    int cy = min(max((int)floorf(qi.y * INV_CELL), 0), GRID1 - 1);
    int cz = min(max((int)floorf(qi.z * INV_CELL), 0), GRID1 - 1);
    int zlo = max(cz - 1, 0), zhi = min(cz + 1, GRID1 - 1);

    float acc = 0.0f;
    int cnt_sim = 0, cnt_nb = 0, nhit = 0;

    // ---- Phase A: scan 9 (x,y) rows of the 3x3x3 neighborhood ----
    for (int dx = -1; dx <= 1; dx++) {
        int X = cx + dx;
        if ((unsigned)X >= GRID1) continue;
        for (int dy = -1; dy <= 1; dy++) {
            int Y = cy + dy;
            if ((unsigned)Y >= GRID1) continue;
            int row = (X * GRID1 + Y) * GRID1;
            int s0 = cs[row + zlo];
            int s1 = cs[row + zhi + 1];
            for (int sbase = s0; sbase < s1; sbase += 32) {
                int s = sbase + lane;
                bool act = (s < s1);
                float4 qj;
                if (act) qj = g_bq[sb_ + s];
                else { qj.x = 1e9f; qj.y = 1e9f; qj.z = 1e9f; qj.w = 3e18f; }
                float g  = __fmaf_rn(qi.z, qj.z,
                           __fmaf_rn(qi.y, qj.y,
                           __fmul_rn(qi.x, qj.x)));
                float d2 = __fadd_rn(__fadd_rn(qi.w, qj.w), __fmul_rn(-2.0f, g));
                bool hit = act && (d2 < RADIUS2);
                unsigned m = __ballot_sync(FULLMASK, hit);
                int nh = __popc(m);
                cnt_nb += nh;
                int jj = 0;
                if (hit) jj = (int)g_bidx[sb_ + s];
                if (nhit + nh <= HL_CAP) {
                    if (hit)
                        myhl[nhit + __popc(m & ((1u << lane) - 1u))] =
                            (unsigned short)jj;
                    nhit += nh;
                } else {
                    // overflow: process inline (pathological inputs only)
                    while (m) {
                        int l = __ffs(m) - 1; m &= m - 1;
                        int j = __shfl_sync(FULLMASK, jj, l);
                        float v = embb[j * DIM + lane];
                        float p = __fmul_rn(v, ei);
                        #pragma unroll
                        for (int o = 16; o; o >>= 1)
                            p += __shfl_xor_sync(FULLMASK, p, o);
                        float sim = __fdiv_rn(p, __fmul_rn(ni, normb[j]));
                        if (sim > SIM_T) { acc += v; cnt_sim++; }
                    }
                }
            }
        }
    }

    // ---- sort hit list ascending by original index (deterministic order) ----
    if (nhit <= 32) {
        int v = (lane < nhit) ? (int)myhl[lane] : 0x10000;
        #pragma unroll
        for (int k = 2; k <= 32; k <<= 1) {
            #pragma unroll
            for (int j = k >> 1; j > 0; j >>= 1) {
                int o = __shfl_xor_sync(FULLMASK, v, j);
                bool up    = ((lane & k) == 0);
                bool lower = ((lane & j) == 0);
                v = (up == lower) ? min(v, o) : max(v, o);
            }
        }
        if (lane < nhit) myhl[lane] = (unsigned short)v;
    } else if (lane == 0) {                      // rare path
        for (int a = 1; a < nhit; a++) {
            unsigned short key = myhl[a];
            int c = a - 1;
            while (c >= 0 && myhl[c] > key) { myhl[c + 1] = myhl[c]; c--; }
            myhl[c + 1] = key;
        }
    }
    __syncwarp();

    // ---- Phase B: 8-way interleaved similarity reductions ----
    for (int t = 0; t < nhit; t += 8) {
        int jx[8];
        float vx[8], px[8];
        #pragma unroll
        for (int k = 0; k < 8; k++)
            jx[k] = myhl[min(t + k, nhit - 1)];
        #pragma unroll
        for (int k = 0; k < 8; k++) {
            vx[k] = embb[jx[k] * DIM + lane];
            px[k] = __fmul_rn(vx[k], ei);
        }
        #pragma unroll
        for (int o = 16; o; o >>= 1) {
            #pragma unroll
            for (int k = 0; k < 8; k++)
                px[k] += __shfl_xor_sync(FULLMASK, px[k], o);
        }
        #pragma unroll
        for (int k = 0; k < 8; k++) {
            if (t + k < nhit) {
                float sim = __fdiv_rn(px[k], __fmul_rn(ni, normb[jx[k]]));
                if (sim > SIM_T) { acc += vx[k]; cnt_sim++; }
            }
        }
    }

    float mean = acc / (float)max(cnt_sim, 1);

    // ---- MLP (smem weights; 4 partial accumulator chains) ----
    float h0 = sb1[lane], h1 = 0.0f, h2 = 0.0f, h3 = 0.0f;
    #pragma unroll
    for (int k = 0; k < 8; k++) {
        h0 = __fmaf_rn(__shfl_sync(FULLMASK, ei, k),      sW1[(k)      * DIM + lane], h0);
        h1 = __fmaf_rn(__shfl_sync(FULLMASK, ei, k + 8),  sW1[(k + 8)  * DIM + lane], h1);
        h2 = __fmaf_rn(__shfl_sync(FULLMASK, ei, k + 16), sW1[(k + 16) * DIM + lane], h2);
        h3 = __fmaf_rn(__shfl_sync(FULLMASK, ei, k + 24), sW1[(k + 24) * DIM + lane], h3);
    }
    #pragma unroll
    for (int k = 0; k < 8; k++) {
        h0 = __fmaf_rn(__shfl_sync(FULLMASK, mean, k),      sW1[(k + 32) * DIM + lane], h0);
        h1 = __fmaf_rn(__shfl_sync(FULLMASK, mean, k + 8),  sW1[(k + 40) * DIM + lane], h1);
        h2 = __fmaf_rn(__shfl_sync(FULLMASK, mean, k + 16), sW1[(k + 48) * DIM + lane], h2);
        h3 = __fmaf_rn(__shfl_sync(FULLMASK, mean, k + 24), sW1[(k + 56) * DIM + lane], h3);
    }
    float h = fmaxf((h0 + h1) + (h2 + h3), 0.0f);

    float o0 = sb2[lane], o1 = 0.0f, o2 = 0.0f, o3 = 0.0f;
    #pragma unroll
    for (int k = 0; k < 8; k++) {
        o0 = __fmaf_rn(__shfl_sync(FULLMASK, h, k),      sW2[(k)      * DIM + lane], o0);
        o1 = __fmaf_rn(__shfl_sync(FULLMASK, h, k + 8),  sW2[(k + 8)  * DIM + lane], o1);
        o2 = __fmaf_rn(__shfl_sync(FULLMASK, h, k + 16), sW2[(k + 16) * DIM + lane], o2);
        o3 = __fmaf_rn(__shfl_sync(FULLMASK, h, k + 24), sW2[(k + 24) * DIM + lane], o3);
    }
    float o = (o0 + o1) + (o2 + o3);

    if (cnt_nb > 1 && cnt_sim > 0)
        out[gi * DIM + lane] = o;
}

// ---------------------------------------------------------------------------
extern "C" void kernel_launch(void* const* d_in, const int* in_sizes, int n_in,
                              void* d_out, int out_size)
{
    const float* points    = (const float*)d_in[0];
    const float* emb       = (const float*)d_in[1];
    const int*   leaf_mask = (const int*)  d_in[2];
    const float* W1        = (const float*)d_in[3];
    const float* b1        = (const float*)d_in[4];
    const float* W2        = (const float*)d_in[5];
    const float* b2        = (const float*)d_in[6];
    float* out = (float*)d_out;

    prep_kernel<<<(PREP_THR + 255) / 256, 256>>>(points, emb, leaf_mask, out);
    scan_kernel<<<BATCH, 1024>>>();
    scatter_kernel<<<(NP + 255) / 256, 256>>>();

    dim3 grid((NPTS + MWPB - 1) / MWPB, BATCH);
    main_kernel<<<grid, MT>>>(emb, W1, b1, W2, b2, out);
}

// round 11
// speedup vs baseline: 1.5444x; 1.5444x over previous
#include <cuda_runtime.h>
#include <cuda_bf16.h>

#define BATCH   2
#define NPTS    6144
#define DIM     32
#define RADIUS2 0.0009f      // 0.03^2
#define SIM_T   0.7f
#define EPS_N   1e-8f
#define FULLMASK 0xffffffffu

#define GRID1   10           // cells per axis
#define NCELLS  1000
#define INV_CELL 33.0f       // cell width = 1/33 = 0.0303 > radius (robust margin)

#define HL_CAP  96           // per-warp hit list (expected hits ~13)
#define MT      512          // main kernel threads
#define MWPB    (MT / 32)    // 16 warps per block

// -------- scratch (__device__ globals; no allocation allowed) --------
__device__ float4 g_q[BATCH * NPTS];            // (x,y,z,|p|^2) per point
__device__ float  g_norm[BATCH * NPTS];         // max(||emb||, eps)
__device__ int    g_cell[BATCH * NPTS];         // cell id if leaf, -1 if not
__device__ int    g_hist[BATCH * NCELLS];       // zero-init; re-armed by binscatter
__device__ float4 g_bq[BATCH * NPTS];           // binned leaf points
__device__ unsigned short g_bidx[BATCH * NPTS]; // binned -> original local idx
__device__ int    g_cellstart[BATCH * (NCELLS + 1)];
__device__ int    g_leaf_cnt[BATCH];

__device__ __forceinline__ int cell_of(float x, float y, float z) {
    int cx = (int)floorf(x * INV_CELL);
    int cy = (int)floorf(y * INV_CELL);
    int cz = (int)floorf(z * INV_CELL);
    cx = min(max(cx, 0), GRID1 - 1);
    cy = min(max(cy, 0), GRID1 - 1);
    cz = min(max(cz, 0), GRID1 - 1);
    return (cx * GRID1 + cy) * GRID1 + cz;
}

// ---------------------------------------------------------------------------
// Kernel 1: prep (role-split). EXACT R4 version (29.2us config).
//   copy role : 4 independent float4s per thread  (out = emb)
//   point role: 1 point per thread -> norm, g_q, g_cell, histogram atomics
// ---------------------------------------------------------------------------
#define NP        (BATCH * NPTS)                 // 12288 points
#define COPY_THR  (NP * 8 / 4)                   // 24576 copy threads
#define PREP_THR  (COPY_THR + NP)

__global__ __launch_bounds__(256) void prep_kernel(
    const float* __restrict__ points,
    const float* __restrict__ emb,
    const int*   __restrict__ leaf_mask,
    float*       __restrict__ out)
{
    int tid = blockIdx.x * blockDim.x + threadIdx.x;
    if (tid < COPY_THR) {
        const float4* src = (const float4*)emb;
        float4*       dst = (float4*)out;
        int base = tid * 4;
        float4 v0 = src[base + 0];
        float4 v1 = src[base + 1];
        float4 v2 = src[base + 2];
        float4 v3 = src[base + 3];
        dst[base + 0] = v0;
        dst[base + 1] = v1;
        dst[base + 2] = v2;
        dst[base + 3] = v3;
        return;
    }
    int p = tid - COPY_THR;
    if (p >= NP) return;

    const float4* e4 = (const float4*)(emb) + p * 8;
    float s = 0.0f;
    #pragma unroll
    for (int k = 0; k < 8; k++) {
        float4 v = e4[k];
        s += __fmaf_rn(v.w, v.w,
             __fmaf_rn(v.z, v.z,
             __fmaf_rn(v.y, v.y, __fmul_rn(v.x, v.x))));
    }
    g_norm[p] = fmaxf(sqrtf(s), EPS_N);

    float x = points[p * 3 + 0];
    float y = points[p * 3 + 1];
    float z = points[p * 3 + 2];
    float pn = __fadd_rn(__fadd_rn(__fmul_rn(x, x), __fmul_rn(y, y)),
                         __fmul_rn(z, z));
    g_q[p] = make_float4(x, y, z, pn);

    int b = p / NPTS;
    if (leaf_mask[p] > 0) {
        int c = cell_of(x, y, z);
        g_cell[p] = c;
        atomicAdd(&g_hist[b * NCELLS + c], 1);
    } else {
        g_cell[p] = -1;
    }
}

// ---------------------------------------------------------------------------
// Kernel 2: binscatter (fused scan + scatter). One 1024-thread block/batch.
//  - warp-shuffle scan of histogram -> cellstart, leaf_cnt (+ re-arm hist)
//  - scatter points via smem cursors (order nondeterministic; main's bitonic
//    hit-list sort restores determinism, as proven at 29.2us)
// ---------------------------------------------------------------------------
__global__ __launch_bounds__(1024) void binscatter_kernel()
{
    int b = blockIdx.x;
    int t = threadIdx.x;
    int lane = t & 31, wrp = t >> 5;

    __shared__ int scur[NCELLS];
    __shared__ int wsum[32];

    // ---- load + re-arm histogram ----
    int h = 0;
    if (t < NCELLS) {
        h = g_hist[b * NCELLS + t];
        g_hist[b * NCELLS + t] = 0;
    }

    // ---- 2-level warp-shuffle inclusive scan over 1024 lanes ----
    int v = h;
    #pragma unroll
    for (int o = 1; o < 32; o <<= 1) {
        int u = __shfl_up_sync(FULLMASK, v, o);
        if (lane >= o) v += u;
    }
    if (lane == 31) wsum[wrp] = v;
    __syncthreads();
    if (wrp == 0) {
        int sv = wsum[lane];
        #pragma unroll
        for (int o = 1; o < 32; o <<= 1) {
            int u = __shfl_up_sync(FULLMASK, sv, o);
            if (lane >= o) sv += u;
        }
        wsum[lane] = sv;
    }
    __syncthreads();
    int incl = v + ((wrp > 0) ? wsum[wrp - 1] : 0);

    if (t < NCELLS) {
        int start = incl - h;                    // exclusive prefix
        scur[t] = start;
        g_cellstart[b * (NCELLS + 1) + t] = start;
    }
    if (t == NCELLS - 1) {
        g_cellstart[b * (NCELLS + 1) + NCELLS] = incl;
        g_leaf_cnt[b] = incl;
    }
    __syncthreads();

    // ---- scatter with smem cursors (6 points/thread) ----
    const int PER = NPTS / 1024;                 // 6
    int base = b * NPTS + t * PER;
    #pragma unroll
    for (int k = 0; k < PER; k++) {
        int c = g_cell[base + k];
        if (c >= 0) {
            int slot = atomicAdd(&scur[c], 1);
            g_bq[b * NPTS + slot]   = g_q[base + k];
            g_bidx[b * NPTS + slot] = (unsigned short)(base + k - b * NPTS);
        }
    }
}

// ---------------------------------------------------------------------------
// Kernel 3: main. EXACT R4 version (22.5us measured; regs 40) minus the
// hist re-zero (done by binscatter now). One warp per binned leaf query.
// ---------------------------------------------------------------------------
__global__ __launch_bounds__(MT) void main_kernel(
    const float* __restrict__ emb,
    const float* __restrict__ W1,
    const float* __restrict__ b1,
    const float* __restrict__ W2,
    const float* __restrict__ b2,
    float*       __restrict__ out)
{
    __shared__ float sW1[64 * 32];
    __shared__ float sW2[32 * 32];
    __shared__ float sb1[32], sb2[32];
    __shared__ unsigned short hl[MWPB * HL_CAP];

    int b   = blockIdx.y;
    int cnt = g_leaf_cnt[b];
    if (cnt < 10) return;                        // batch early-exit (uniform)
    int warp0 = blockIdx.x * MWPB;
    if (warp0 >= cnt) return;                    // dead block (uniform)

    // stage MLP weights (live blocks only)
    for (int k = threadIdx.x; k < 64 * 32; k += MT) sW1[k] = W1[k];
    for (int k = threadIdx.x; k < 32 * 32; k += MT) sW2[k] = W2[k];
    if (threadIdx.x < 32) { sb1[threadIdx.x] = b1[threadIdx.x];
                            sb2[threadIdx.x] = b2[threadIdx.x]; }
    __syncthreads();

    int wid  = threadIdx.x >> 5;
    int lane = threadIdx.x & 31;
    int w    = warp0 + wid;
    if (w >= cnt) return;

    int sb_ = b * NPTS;
    float4 qi = g_bq[sb_ + w];
    int    i  = g_bidx[sb_ + w];
    int    gi = sb_ + i;

    float ni = g_norm[gi];
    float ei = emb[gi * DIM + lane];

    const float* embb  = emb    + sb_ * DIM;
    const float* normb = g_norm + sb_;
    const int*   cs    = g_cellstart + b * (NCELLS + 1);
    unsigned short* myhl = hl + wid * HL_CAP;

    int cx = min(max((int)floorf(qi.x * INV_CELL), 0), GRID1 - 1);
    int cy = min(max((int)floorf(qi.y * INV_CELL), 0), GRID1 - 1);
    int cz = min(max((int)floorf(qi.z * INV_CELL), 0), GRID1 - 1);
    int zlo = max(cz - 1, 0), zhi = min(cz + 1, GRID1 - 1);

    float acc = 0.0f;
    int cnt_sim = 0, cnt_nb = 0, nhit = 0;

    // ---- Phase A: scan 9 (x,y) rows of the 3x3x3 neighborhood ----
    for (int dx = -1; dx <= 1; dx++) {
        int X = cx + dx;
        if ((unsigned)X >= GRID1) continue;
        for (int dy = -1; dy <= 1; dy++) {
            int Y = cy + dy;
            if ((unsigned)Y >= GRID1) continue;
            int row = (X * GRID1 + Y) * GRID1;
            int s0 = cs[row + zlo];
            int s1 = cs[row + zhi + 1];
            for (int sbase = s0; sbase < s1; sbase += 32) {
                int s = sbase + lane;
                bool act = (s < s1);
                float4 qj;
                if (act) qj = g_bq[sb_ + s];
                else { qj.x = 1e9f; qj.y = 1e9f; qj.z = 1e9f; qj.w = 3e18f; }
                float g  = __fmaf_rn(qi.z, qj.z,
                           __fmaf_rn(qi.y, qj.y,
                           __fmul_rn(qi.x, qj.x)));
                float d2 = __fadd_rn(__fadd_rn(qi.w, qj.w), __fmul_rn(-2.0f, g));
                bool hit = act && (d2 < RADIUS2);
                unsigned m = __ballot_sync(FULLMASK, hit);
                int nh = __popc(m);
                cnt_nb += nh;
                int jj = 0;
                if (hit) jj = (int)g_bidx[sb_ + s];
                if (nhit + nh <= HL_CAP) {
                    if (hit)
                        myhl[nhit + __popc(m & ((1u << lane) - 1u))] =
                            (unsigned short)jj;
                    nhit += nh;
                } else {
                    // overflow: process inline (pathological inputs only)
                    while (m) {
                        int l = __ffs(m) - 1; m &= m - 1;
                        int j = __shfl_sync(FULLMASK, jj, l);
                        float v = embb[j * DIM + lane];
                        float p = __fmul_rn(v, ei);
                        #pragma unroll
                        for (int o = 16; o; o >>= 1)
                            p += __shfl_xor_sync(FULLMASK, p, o);
                        float sim = __fdiv_rn(p, __fmul_rn(ni, normb[j]));
                        if (sim > SIM_T) { acc += v; cnt_sim++; }
                    }
                }
            }
        }
    }

    // ---- sort hit list ascending by original index (deterministic order) ----
    if (nhit <= 32) {
        int v = (lane < nhit) ? (int)myhl[lane] : 0x10000;
        #pragma unroll
        for (int k = 2; k <= 32; k <<= 1) {
            #pragma unroll
            for (int j = k >> 1; j > 0; j >>= 1) {
                int o = __shfl_xor_sync(FULLMASK, v, j);
                bool up    = ((lane & k) == 0);
                bool lower = ((lane & j) == 0);
                v = (up == lower) ? min(v, o) : max(v, o);
            }
        }
        if (lane < nhit) myhl[lane] = (unsigned short)v;
    } else if (lane == 0) {                      // rare path
        for (int a = 1; a < nhit; a++) {
            unsigned short key = myhl[a];
            int c = a - 1;
            while (c >= 0 && myhl[c] > key) { myhl[c + 1] = myhl[c]; c--; }
            myhl[c + 1] = key;
        }
    }
    __syncwarp();

    // ---- Phase B: 4-way interleaved similarity reductions ----
    for (int t = 0; t < nhit; t += 4) {
        int r = nhit - t;
        int j0 = myhl[t];
        int j1 = myhl[t + ((r > 1) ? 1 : 0)];
        int j2 = myhl[t + ((r > 2) ? 2 : 0)];
        int j3 = myhl[t + ((r > 3) ? 3 : 0)];

        float v0 = embb[j0 * DIM + lane];
        float v1 = embb[j1 * DIM + lane];
        float v2 = embb[j2 * DIM + lane];
        float v3 = embb[j3 * DIM + lane];
        float n0 = normb[j0], n1 = normb[j1], n2 = normb[j2], n3 = normb[j3];

        float p0 = __fmul_rn(v0, ei);
        float p1 = __fmul_rn(v1, ei);
        float p2 = __fmul_rn(v2, ei);
        float p3 = __fmul_rn(v3, ei);
        #pragma unroll
        for (int o = 16; o; o >>= 1) {
            p0 += __shfl_xor_sync(FULLMASK, p0, o);
            p1 += __shfl_xor_sync(FULLMASK, p1, o);
            p2 += __shfl_xor_sync(FULLMASK, p2, o);
            p3 += __shfl_xor_sync(FULLMASK, p3, o);
        }
        float s0 = __fdiv_rn(p0, __fmul_rn(ni, n0));
        float s1 = __fdiv_rn(p1, __fmul_rn(ni, n1));
        float s2 = __fdiv_rn(p2, __fmul_rn(ni, n2));
        float s3 = __fdiv_rn(p3, __fmul_rn(ni, n3));

        if (s0 > SIM_T)          { acc += v0; cnt_sim++; }
        if (r > 1 && s1 > SIM_T) { acc += v1; cnt_sim++; }
        if (r > 2 && s2 > SIM_T) { acc += v2; cnt_sim++; }
        if (r > 3 && s3 > SIM_T) { acc += v3; cnt_sim++; }
    }

    float mean = acc / (float)max(cnt_sim, 1);

    // ---- MLP: h = relu([emb_i, mean] @ W1 + b1); o = h @ W2 + b2 ----
    float h = sb1[lane];
    #pragma unroll
    for (int k = 0; k < 32; k++) {
        float ck = __shfl_sync(FULLMASK, ei, k);
        h = __fmaf_rn(ck, sW1[k * DIM + lane], h);
    }
    #pragma unroll
    for (int k = 0; k < 32; k++) {
        float ck = __shfl_sync(FULLMASK, mean, k);
        h = __fmaf_rn(ck, sW1[(k + 32) * DIM + lane], h);
    }
    h = fmaxf(h, 0.0f);

    float o = sb2[lane];
    #pragma unroll
    for (int k = 0; k < 32; k++) {
        float hk = __shfl_sync(FULLMASK, h, k);
        o = __fmaf_rn(hk, sW2[k * DIM + lane], o);
    }

    if (cnt_nb > 1 && cnt_sim > 0)
        out[gi * DIM + lane] = o;
}

// ---------------------------------------------------------------------------
extern "C" void kernel_launch(void* const* d_in, const int* in_sizes, int n_in,
                              void* d_out, int out_size)
{
    const float* points    = (const float*)d_in[0];
    const float* emb       = (const float*)d_in[1];
    const int*   leaf_mask = (const int*)  d_in[2];
    const float* W1        = (const float*)d_in[3];
    const float* b1        = (const float*)d_in[4];
    const float* W2        = (const float*)d_in[5];
    const float* b2        = (const float*)d_in[6];
    float* out = (float*)d_out;

    prep_kernel<<<(PREP_THR + 255) / 256, 256>>>(points, emb, leaf_mask, out);
    binscatter_kernel<<<BATCH, 1024>>>();

    dim3 grid((NPTS + MWPB - 1) / MWPB, BATCH);
    main_kernel<<<grid, MT>>>(emb, W1, b1, W2, b2, out);
}

// round 13
// speedup vs baseline: 1.9068x; 1.2347x over previous
#include <cuda_runtime.h>
#include <cuda_bf16.h>

#define BATCH   2
#define NPTS    6144
#define DIM     32
#define RADIUS2 0.0009f      // 0.03^2
#define SIM_T   0.7f
#define EPS_N   1e-8f
#define FULLMASK 0xffffffffu

#define GRID1   10           // cells per axis
#define NCELLS  1000
#define INV_CELL 33.0f       // cell width = 1/33 = 0.0303 > radius (robust margin)

#define HL_CAP  96           // per-warp hit list (expected hits ~13)
#define MT      512          // main kernel threads
#define MWPB    (MT / 32)    // 16 warps per block

// -------- scratch (__device__ globals; no allocation allowed) --------
__device__ float4 g_q[BATCH * NPTS];            // (x,y,z,|p|^2) per point
__device__ float  g_norm[BATCH * NPTS];         // max(||emb||, eps)
__device__ int    g_cell[BATCH * NPTS];         // cell id if leaf, -1 if not
__device__ int    g_hist[BATCH * NCELLS];       // zero-init; re-zeroed by main
__device__ int    g_cur[BATCH * NCELLS];        // scatter cursors (set by scan)
__device__ float4 g_bq[BATCH * NPTS];           // binned leaf points
__device__ unsigned short g_bidx[BATCH * NPTS]; // binned -> original local idx
__device__ int    g_cellstart[BATCH * (NCELLS + 1)];
__device__ int    g_leaf_cnt[BATCH];

__device__ __forceinline__ int cell_of(float x, float y, float z) {
    int cx = (int)floorf(x * INV_CELL);
    int cy = (int)floorf(y * INV_CELL);
    int cz = (int)floorf(z * INV_CELL);
    cx = min(max(cx, 0), GRID1 - 1);
    cy = min(max(cy, 0), GRID1 - 1);
    cz = min(max(cz, 0), GRID1 - 1);
    return (cx * GRID1 + cy) * GRID1 + cz;
}

// ---------------------------------------------------------------------------
// Kernel 1: prep (role-split). EXACT R4 version.
//   copy role : 4 independent float4s per thread  (out = emb)
//   point role: 1 point per thread -> norm, g_q, g_cell, histogram atomics
// ---------------------------------------------------------------------------
#define NP        (BATCH * NPTS)                 // 12288 points
#define COPY_THR  (NP * 8 / 4)                   // 24576 copy threads
#define PREP_THR  (COPY_THR + NP)

__global__ __launch_bounds__(256) void prep_kernel(
    const float* __restrict__ points,
    const float* __restrict__ emb,
    const int*   __restrict__ leaf_mask,
    float*       __restrict__ out)
{
    int tid = blockIdx.x * blockDim.x + threadIdx.x;
    if (tid < COPY_THR) {
        const float4* src = (const float4*)emb;
        float4*       dst = (float4*)out;
        int base = tid * 4;
        float4 v0 = src[base + 0];
        float4 v1 = src[base + 1];
        float4 v2 = src[base + 2];
        float4 v3 = src[base + 3];
        dst[base + 0] = v0;
        dst[base + 1] = v1;
        dst[base + 2] = v2;
        dst[base + 3] = v3;
        return;
    }
    int p = tid - COPY_THR;
    if (p >= NP) return;

    const float4* e4 = (const float4*)(emb) + p * 8;
    float s = 0.0f;
    #pragma unroll
    for (int k = 0; k < 8; k++) {
        float4 v = e4[k];
        s += __fmaf_rn(v.w, v.w,
             __fmaf_rn(v.z, v.z,
             __fmaf_rn(v.y, v.y, __fmul_rn(v.x, v.x))));
    }
    g_norm[p] = fmaxf(sqrtf(s), EPS_N);

    float x = points[p * 3 + 0];
    float y = points[p * 3 + 1];
    float z = points[p * 3 + 2];
    float pn = __fadd_rn(__fadd_rn(__fmul_rn(x, x), __fmul_rn(y, y)),
                         __fmul_rn(z, z));
    g_q[p] = make_float4(x, y, z, pn);

    int b = p / NPTS;
    if (leaf_mask[p] > 0) {
        int c = cell_of(x, y, z);
        g_cell[p] = c;
        atomicAdd(&g_hist[b * NCELLS + c], 1);
    } else {
        g_cell[p] = -1;
    }
}

// ---------------------------------------------------------------------------
// Kernel 2: scan histogram -> cellstart + cursors + leaf_cnt. One block/batch.
// EXACT R4 version.
// ---------------------------------------------------------------------------
__global__ __launch_bounds__(1024) void scan_kernel()
{
    int b = blockIdx.x;
    int t = threadIdx.x;
    __shared__ int sc[1024];

    int h = (t < NCELLS) ? g_hist[b * NCELLS + t] : 0;
    sc[t] = h;
    __syncthreads();
    for (int d = 1; d < 1024; d <<= 1) {
        int v = (t >= d) ? sc[t - d] : 0;
        __syncthreads();
        sc[t] += v;
        __syncthreads();
    }
    if (t < NCELLS) {
        int start = sc[t] - h;                   // exclusive prefix
        g_cellstart[b * (NCELLS + 1) + t] = start;
        g_cur[b * NCELLS + t] = start;
    }
    if (t == NCELLS - 1) {
        g_cellstart[b * (NCELLS + 1) + NCELLS] = sc[t];
        g_leaf_cnt[b] = sc[t];
    }
}

// ---------------------------------------------------------------------------
// Kernel 3: parallel scatter. One thread per point. EXACT R4 version.
// (Within-cell order nondeterministic; tolerated — rel_err validation.)
// ---------------------------------------------------------------------------
__global__ __launch_bounds__(256) void scatter_kernel()
{
    int p = blockIdx.x * blockDim.x + threadIdx.x;
    if (p >= NP) return;
    int c = g_cell[p];
    if (c < 0) return;
    int b = p / NPTS;
    int slot = atomicAdd(&g_cur[b * NCELLS + c], 1);
    g_bq[b * NPTS + slot]   = g_q[p];
    g_bidx[b * NPTS + slot] = (unsigned short)(p - b * NPTS);
}

// ---------------------------------------------------------------------------
// Kernel 4: main. EXACT R4 version with ONE deletion: the bitonic hit-list
// sort (pure latency; order-nondeterminism is tolerated, cf. Round-1 pass).
// One warp per binned leaf query. Re-zeroes g_hist for next replay.
// ---------------------------------------------------------------------------
__global__ __launch_bounds__(MT) void main_kernel(
    const float* __restrict__ emb,
    const float* __restrict__ W1,
    const float* __restrict__ b1,
    const float* __restrict__ W2,
    const float* __restrict__ b2,
    float*       __restrict__ out)
{
    __shared__ float sW1[64 * 32];
    __shared__ float sW2[32 * 32];
    __shared__ float sb1[32], sb2[32];
    __shared__ unsigned short hl[MWPB * HL_CAP];

    // re-zero histogram for next replay (hist already consumed by scan)
    if (blockIdx.x == 0 && blockIdx.y == 0) {
        for (int k = threadIdx.x; k < BATCH * NCELLS; k += MT) g_hist[k] = 0;
    }

    int b   = blockIdx.y;
    int cnt = g_leaf_cnt[b];
    if (cnt < 10) return;                        // batch early-exit (uniform)
    int warp0 = blockIdx.x * MWPB;
    if (warp0 >= cnt) return;                    // dead block (uniform)

    // stage MLP weights (live blocks only)
    for (int k = threadIdx.x; k < 64 * 32; k += MT) sW1[k] = W1[k];
    for (int k = threadIdx.x; k < 32 * 32; k += MT) sW2[k] = W2[k];
    if (threadIdx.x < 32) { sb1[threadIdx.x] = b1[threadIdx.x];
                            sb2[threadIdx.x] = b2[threadIdx.x]; }
    __syncthreads();

    int wid  = threadIdx.x >> 5;
    int lane = threadIdx.x & 31;
    int w    = warp0 + wid;
    if (w >= cnt) return;

    int sb_ = b * NPTS;
    float4 qi = g_bq[sb_ + w];
    int    i  = g_bidx[sb_ + w];
    int    gi = sb_ + i;

    float ni = g_norm[gi];
    float ei = emb[gi * DIM + lane];

    const float* embb  = emb    + sb_ * DIM;
    const float* normb = g_norm + sb_;
    const int*   cs    = g_cellstart + b * (NCELLS + 1);
    unsigned short* myhl = hl + wid * HL_CAP;

    int cx = min(max((int)floorf(qi.x * INV_CELL), 0), GRID1 - 1);
    int cy = min(max((int)floorf(qi.y * INV_CELL), 0), GRID1 - 1);
    int cz = min(max((int)floorf(qi.z * INV_CELL), 0), GRID1 - 1);
    int zlo = max(cz - 1, 0), zhi = min(cz + 1, GRID1 - 1);

    float acc = 0.0f;
    int cnt_sim = 0, cnt_nb = 0, nhit = 0;

    // ---- Phase A: scan 9 (x,y) rows of the 3x3x3 neighborhood ----
    for (int dx = -1; dx <= 1; dx++) {
        int X = cx + dx;
        if ((unsigned)X >= GRID1) continue;
        for (int dy = -1; dy <= 1; dy++) {
            int Y = cy + dy;
            if ((unsigned)Y >= GRID1) continue;
            int row = (X * GRID1 + Y) * GRID1;
            int s0 = cs[row + zlo];
            int s1 = cs[row + zhi + 1];
            for (int sbase = s0; sbase < s1; sbase += 32) {
                int s = sbase + lane;
                bool act = (s < s1);
                float4 qj;
                if (act) qj = g_bq[sb_ + s];
                else { qj.x = 1e9f; qj.y = 1e9f; qj.z = 1e9f; qj.w = 3e18f; }
                float g  = __fmaf_rn(qi.z, qj.z,
                           __fmaf_rn(qi.y, qj.y,
                           __fmul_rn(qi.x, qj.x)));
                float d2 = __fadd_rn(__fadd_rn(qi.w, qj.w), __fmul_rn(-2.0f, g));
                bool hit = act && (d2 < RADIUS2);
                unsigned m = __ballot_sync(FULLMASK, hit);
                int nh = __popc(m);
                cnt_nb += nh;
                int jj = 0;
                if (hit) jj = (int)g_bidx[sb_ + s];
                if (nhit + nh <= HL_CAP) {
                    if (hit)
                        myhl[nhit + __popc(m & ((1u << lane) - 1u))] =
                            (unsigned short)jj;
                    nhit += nh;
                } else {
                    // overflow: process inline (pathological inputs only)
                    while (m) {
                        int l = __ffs(m) - 1; m &= m - 1;
                        int j = __shfl_sync(FULLMASK, jj, l);
                        float v = embb[j * DIM + lane];
                        float p = __fmul_rn(v, ei);
                        #pragma unroll
                        for (int o = 16; o; o >>= 1)
                            p += __shfl_xor_sync(FULLMASK, p, o);
                        float sim = __fdiv_rn(p, __fmul_rn(ni, normb[j]));
                        if (sim > SIM_T) { acc += v; cnt_sim++; }
                    }
                }
            }
        }
    }
    __syncwarp();

    // ---- Phase B: 4-way interleaved similarity reductions ----
    for (int t = 0; t < nhit; t += 4) {
        int r = nhit - t;
        int j0 = myhl[t];
        int j1 = myhl[t + ((r > 1) ? 1 : 0)];
        int j2 = myhl[t + ((r > 2) ? 2 : 0)];
        int j3 = myhl[t + ((r > 3) ? 3 : 0)];

        float v0 = embb[j0 * DIM + lane];
        float v1 = embb[j1 * DIM + lane];
        float v2 = embb[j2 * DIM + lane];
        float v3 = embb[j3 * DIM + lane];
        float n0 = normb[j0], n1 = normb[j1], n2 = normb[j2], n3 = normb[j3];

        float p0 = __fmul_rn(v0, ei);
        float p1 = __fmul_rn(v1, ei);
        float p2 = __fmul_rn(v2, ei);
        float p3 = __fmul_rn(v3, ei);
        #pragma unroll
        for (int o = 16; o; o >>= 1) {
            p0 += __shfl_xor_sync(FULLMASK, p0, o);
            p1 += __shfl_xor_sync(FULLMASK, p1, o);
            p2 += __shfl_xor_sync(FULLMASK, p2, o);
            p3 += __shfl_xor_sync(FULLMASK, p3, o);
        }
        float s0 = __fdiv_rn(p0, __fmul_rn(ni, n0));
        float s1 = __fdiv_rn(p1, __fmul_rn(ni, n1));
        float s2 = __fdiv_rn(p2, __fmul_rn(ni, n2));
        float s3 = __fdiv_rn(p3, __fmul_rn(ni, n3));

        if (s0 > SIM_T)          { acc += v0; cnt_sim++; }
        if (r > 1 && s1 > SIM_T) { acc += v1; cnt_sim++; }
        if (r > 2 && s2 > SIM_T) { acc += v2; cnt_sim++; }
        if (r > 3 && s3 > SIM_T) { acc += v3; cnt_sim++; }
    }

    float mean = acc / (float)max(cnt_sim, 1);

    // ---- MLP: h = relu([emb_i, mean] @ W1 + b1); o = h @ W2 + b2 ----
    float h = sb1[lane];
    #pragma unroll
    for (int k = 0; k < 32; k++) {
        float ck = __shfl_sync(FULLMASK, ei, k);
        h = __fmaf_rn(ck, sW1[k * DIM + lane], h);
    }
    #pragma unroll
    for (int k = 0; k < 32; k++) {
        float ck = __shfl_sync(FULLMASK, mean, k);
        h = __fmaf_rn(ck, sW1[(k + 32) * DIM + lane], h);
    }
    h = fmaxf(h, 0.0f);

    float o = sb2[lane];
    #pragma unroll
    for (int k = 0; k < 32; k++) {
        float hk = __shfl_sync(FULLMASK, h, k);
        o = __fmaf_rn(hk, sW2[k * DIM + lane], o);
    }

    if (cnt_nb > 1 && cnt_sim > 0)
        out[gi * DIM + lane] = o;
}

// ---------------------------------------------------------------------------
extern "C" void kernel_launch(void* const* d_in, const int* in_sizes, int n_in,
                              void* d_out, int out_size)
{
    const float* points    = (const float*)d_in[0];
    const float* emb       = (const float*)d_in[1];
    const int*   leaf_mask = (const int*)  d_in[2];
    const float* W1        = (const float*)d_in[3];
    const float* b1        = (const float*)d_in[4];
    const float* W2        = (const float*)d_in[5];
    const float* b2        = (const float*)d_in[6];
    float* out = (float*)d_out;

    prep_kernel<<<(PREP_THR + 255) / 256, 256>>>(points, emb, leaf_mask, out);
    scan_kernel<<<BATCH, 1024>>>();
    scatter_kernel<<<(NP + 255) / 256, 256>>>();

    dim3 grid((NPTS + MWPB - 1) / MWPB, BATCH);
    main_kernel<<<grid, MT>>>(emb, W1, b1, W2, b2, out);
}

// round 14
// speedup vs baseline: 2.0162x; 1.0574x over previous
#include <cuda_runtime.h>
#include <cuda_bf16.h>

#define BATCH   2
#define NPTS    6144
#define DIM     32
#define RADIUS2 0.0009f      // 0.03^2
#define SIM_T   0.7f
#define EPS_N   1e-8f
#define FULLMASK 0xffffffffu

#define GRID1   10           // cells per axis
#define NCELLS  1000
#define INV_CELL 33.0f       // cell width = 1/33 = 0.0303 > radius (robust margin)

#define HL_CAP  96           // per-warp hit list (expected hits ~13)
#define MT      512          // main kernel threads
#define MWPB    (MT / 32)    // 16 warps per block

// -------- scratch (__device__ globals; no allocation allowed) --------
__device__ float4 g_q[BATCH * NPTS];            // (x,y,z,|p|^2) per point
__device__ float  g_norm[BATCH * NPTS];         // max(||emb||, eps)
__device__ int    g_cell[BATCH * NPTS];         // cell id if leaf, -1 if not
__device__ int    g_hist[BATCH * NCELLS];       // zero-init; re-zeroed by main
__device__ int    g_cur[BATCH * NCELLS];        // scatter cursors (set by scan)
__device__ float4 g_bq[BATCH * NPTS];           // binned leaf points
__device__ unsigned short g_bidx[BATCH * NPTS]; // binned -> original local idx
__device__ int    g_cellstart[BATCH * (NCELLS + 1)];
__device__ int    g_leaf_cnt[BATCH];

__device__ __forceinline__ int cell_of(float x, float y, float z) {
    int cx = (int)floorf(x * INV_CELL);
    int cy = (int)floorf(y * INV_CELL);
    int cz = (int)floorf(z * INV_CELL);
    cx = min(max(cx, 0), GRID1 - 1);
    cy = min(max(cy, 0), GRID1 - 1);
    cz = min(max(cz, 0), GRID1 - 1);
    return (cx * GRID1 + cy) * GRID1 + cz;
}

// ---------------------------------------------------------------------------
// Kernel 1: prep (role-split). EXACT R4 version.
// ---------------------------------------------------------------------------
#define NP        (BATCH * NPTS)                 // 12288 points
#define COPY_THR  (NP * 8 / 4)                   // 24576 copy threads
#define PREP_THR  (COPY_THR + NP)

__global__ __launch_bounds__(256) void prep_kernel(
    const float* __restrict__ points,
    const float* __restrict__ emb,
    const int*   __restrict__ leaf_mask,
    float*       __restrict__ out)
{
    int tid = blockIdx.x * blockDim.x + threadIdx.x;
    if (tid < COPY_THR) {
        const float4* src = (const float4*)emb;
        float4*       dst = (float4*)out;
        int base = tid * 4;
        float4 v0 = src[base + 0];
        float4 v1 = src[base + 1];
        float4 v2 = src[base + 2];
        float4 v3 = src[base + 3];
        dst[base + 0] = v0;
        dst[base + 1] = v1;
        dst[base + 2] = v2;
        dst[base + 3] = v3;
        return;
    }
    int p = tid - COPY_THR;
    if (p >= NP) return;

    const float4* e4 = (const float4*)(emb) + p * 8;
    float s = 0.0f;
    #pragma unroll
    for (int k = 0; k < 8; k++) {
        float4 v = e4[k];
        s += __fmaf_rn(v.w, v.w,
             __fmaf_rn(v.z, v.z,
             __fmaf_rn(v.y, v.y, __fmul_rn(v.x, v.x))));
    }
    g_norm[p] = fmaxf(sqrtf(s), EPS_N);

    float x = points[p * 3 + 0];
    float y = points[p * 3 + 1];
    float z = points[p * 3 + 2];
    float pn = __fadd_rn(__fadd_rn(__fmul_rn(x, x), __fmul_rn(y, y)),
                         __fmul_rn(z, z));
    g_q[p] = make_float4(x, y, z, pn);

    int b = p / NPTS;
    if (leaf_mask[p] > 0) {
        int c = cell_of(x, y, z);
        g_cell[p] = c;
        atomicAdd(&g_hist[b * NCELLS + c], 1);
    } else {
        g_cell[p] = -1;
    }
}

// ---------------------------------------------------------------------------
// Kernel 2: scan histogram -> cellstart + cursors + leaf_cnt. EXACT R4.
// ---------------------------------------------------------------------------
__global__ __launch_bounds__(1024) void scan_kernel()
{
    int b = blockIdx.x;
    int t = threadIdx.x;
    __shared__ int sc[1024];

    int h = (t < NCELLS) ? g_hist[b * NCELLS + t] : 0;
    sc[t] = h;
    __syncthreads();
    for (int d = 1; d < 1024; d <<= 1) {
        int v = (t >= d) ? sc[t - d] : 0;
        __syncthreads();
        sc[t] += v;
        __syncthreads();
    }
    if (t < NCELLS) {
        int start = sc[t] - h;                   // exclusive prefix
        g_cellstart[b * (NCELLS + 1) + t] = start;
        g_cur[b * NCELLS + t] = start;
    }
    if (t == NCELLS - 1) {
        g_cellstart[b * (NCELLS + 1) + NCELLS] = sc[t];
        g_leaf_cnt[b] = sc[t];
    }
}

// ---------------------------------------------------------------------------
// Kernel 3: parallel scatter. One thread per point. EXACT R4.
// ---------------------------------------------------------------------------
__global__ __launch_bounds__(256) void scatter_kernel()
{
    int p = blockIdx.x * blockDim.x + threadIdx.x;
    if (p >= NP) return;
    int c = g_cell[p];
    if (c < 0) return;
    int b = p / NPTS;
    int slot = atomicAdd(&g_cur[b * NCELLS + c], 1);
    g_bq[b * NPTS + slot]   = g_q[p];
    g_bidx[b * NPTS + slot] = (unsigned short)(p - b * NPTS);
}

// ---------------------------------------------------------------------------
// Kernel 4: main. Current-best (R13, 21.7us) with ONE change: Phase A uses
// the packed candidate list (lane l<9 owns row segment l; ~3 full ballots
// instead of 9 ragged ones). No sort (order tolerated). Everything else
// byte-identical.
// ---------------------------------------------------------------------------
__global__ __launch_bounds__(MT) void main_kernel(
    const float* __restrict__ emb,
    const float* __restrict__ W1,
    const float* __restrict__ b1,
    const float* __restrict__ W2,
    const float* __restrict__ b2,
    float*       __restrict__ out)
{
    __shared__ float sW1[64 * 32];
    __shared__ float sW2[32 * 32];
    __shared__ float sb1[32], sb2[32];
    __shared__ unsigned short hl[MWPB * HL_CAP];

    // re-zero histogram for next replay (hist already consumed by scan)
    if (blockIdx.x == 0 && blockIdx.y == 0) {
        for (int k = threadIdx.x; k < BATCH * NCELLS; k += MT) g_hist[k] = 0;
    }

    int b   = blockIdx.y;
    int cnt = g_leaf_cnt[b];
    if (cnt < 10) return;                        // batch early-exit (uniform)
    int warp0 = blockIdx.x * MWPB;
    if (warp0 >= cnt) return;                    // dead block (uniform)

    // stage MLP weights (live blocks only)
    for (int k = threadIdx.x; k < 64 * 32; k += MT) sW1[k] = W1[k];
    for (int k = threadIdx.x; k < 32 * 32; k += MT) sW2[k] = W2[k];
    if (threadIdx.x < 32) { sb1[threadIdx.x] = b1[threadIdx.x];
                            sb2[threadIdx.x] = b2[threadIdx.x]; }
    __syncthreads();

    int wid  = threadIdx.x >> 5;
    int lane = threadIdx.x & 31;
    int w    = warp0 + wid;
    if (w >= cnt) return;

    int sb_ = b * NPTS;
    float4 qi = g_bq[sb_ + w];
    int    i  = g_bidx[sb_ + w];
    int    gi = sb_ + i;

    float ni = g_norm[gi];
    float ei = emb[gi * DIM + lane];

    const float* embb  = emb    + sb_ * DIM;
    const float* normb = g_norm + sb_;
    const int*   cs    = g_cellstart + b * (NCELLS + 1);
    unsigned short* myhl = hl + wid * HL_CAP;

    int cx = min(max((int)floorf(qi.x * INV_CELL), 0), GRID1 - 1);
    int cy = min(max((int)floorf(qi.y * INV_CELL), 0), GRID1 - 1);
    int cz = min(max((int)floorf(qi.z * INV_CELL), 0), GRID1 - 1);
    int zlo = max(cz - 1, 0), zhi = min(cz + 1, GRID1 - 1);

    // ---- packed candidate list: lane l<9 owns segment (l/3-1, l%3-1) ----
    int X = cx + (lane / 3) - 1;
    int Y = cy + (lane % 3) - 1;
    bool vseg = (lane < 9) && ((unsigned)X < GRID1) && ((unsigned)Y < GRID1);
    int s0 = 0, len = 0;
    if (vseg) {
        int row = (X * GRID1 + Y) * GRID1;
        s0  = cs[row + zlo];
        len = cs[row + zhi + 1] - s0;
    }
    int cinc = len;                              // inclusive warp scan
    #pragma unroll
    for (int o = 1; o < 32; o <<= 1) {
        int u = __shfl_up_sync(FULLMASK, cinc, o);
        if (lane >= o) cinc += u;
    }
    int total = __shfl_sync(FULLMASK, cinc, 31);
    int cm[8];
    #pragma unroll
    for (int m = 0; m < 8; m++) cm[m] = __shfl_sync(FULLMASK, cinc, m);
    int sdelta = s0 - (cinc - len);              // s0_k - excl_cum_k (lane-held)

    float acc = 0.0f;
    int cnt_sim = 0, cnt_nb = 0, nhit = 0;

    // ---- Phase A: ~3 full chunks over the packed candidate list ----
    for (int vb = 0; vb < total; vb += 32) {
        int v = vb + lane;
        int kk = 0;
        #pragma unroll
        for (int m = 0; m < 8; m++) kk += (v >= cm[m]);
        int s = __shfl_sync(FULLMASK, sdelta, kk) + v;
        bool act = (v < total);
        float4 qj;
        if (act) qj = g_bq[sb_ + s];
        else { qj.x = 1e9f; qj.y = 1e9f; qj.z = 1e9f; qj.w = 3e18f; }
        float g  = __fmaf_rn(qi.z, qj.z,
                   __fmaf_rn(qi.y, qj.y,
                   __fmul_rn(qi.x, qj.x)));
        float d2 = __fadd_rn(__fadd_rn(qi.w, qj.w), __fmul_rn(-2.0f, g));
        bool hit = act && (d2 < RADIUS2);
        unsigned m2 = __ballot_sync(FULLMASK, hit);
        int nh = __popc(m2);
        cnt_nb += nh;
        int jj = 0;
        if (hit) jj = (int)g_bidx[sb_ + s];
        if (nhit + nh <= HL_CAP) {
            if (hit)
                myhl[nhit + __popc(m2 & ((1u << lane) - 1u))] =
                    (unsigned short)jj;
            nhit += nh;
        } else {
            // overflow: process inline (pathological inputs only)
            while (m2) {
                int l = __ffs(m2) - 1; m2 &= m2 - 1;
                int j = __shfl_sync(FULLMASK, jj, l);
                float vv = embb[j * DIM + lane];
                float p = __fmul_rn(vv, ei);
                #pragma unroll
                for (int o = 16; o; o >>= 1)
                    p += __shfl_xor_sync(FULLMASK, p, o);
                float sim = __fdiv_rn(p, __fmul_rn(ni, normb[j]));
                if (sim > SIM_T) { acc += vv; cnt_sim++; }
            }
        }
    }
    __syncwarp();

    // ---- Phase B: 4-way interleaved similarity reductions ----
    for (int t = 0; t < nhit; t += 4) {
        int r = nhit - t;
        int j0 = myhl[t];
        int j1 = myhl[t + ((r > 1) ? 1 : 0)];
        int j2 = myhl[t + ((r > 2) ? 2 : 0)];
        int j3 = myhl[t + ((r > 3) ? 3 : 0)];

        float v0 = embb[j0 * DIM + lane];
        float v1 = embb[j1 * DIM + lane];
        float v2 = embb[j2 * DIM + lane];
        float v3 = embb[j3 * DIM + lane];
        float n0 = normb[j0], n1 = normb[j1], n2 = normb[j2], n3 = normb[j3];

        float p0 = __fmul_rn(v0, ei);
        float p1 = __fmul_rn(v1, ei);
        float p2 = __fmul_rn(v2, ei);
        float p3 = __fmul_rn(v3, ei);
        #pragma unroll
        for (int o = 16; o; o >>= 1) {
            p0 += __shfl_xor_sync(FULLMASK, p0, o);
            p1 += __shfl_xor_sync(FULLMASK, p1, o);
            p2 += __shfl_xor_sync(FULLMASK, p2, o);
            p3 += __shfl_xor_sync(FULLMASK, p3, o);
        }
        float s0_ = __fdiv_rn(p0, __fmul_rn(ni, n0));
        float s1_ = __fdiv_rn(p1, __fmul_rn(ni, n1));
        float s2_ = __fdiv_rn(p2, __fmul_rn(ni, n2));
        float s3_ = __fdiv_rn(p3, __fmul_rn(ni, n3));

        if (s0_ > SIM_T)          { acc += v0; cnt_sim++; }
        if (r > 1 && s1_ > SIM_T) { acc += v1; cnt_sim++; }
        if (r > 2 && s2_ > SIM_T) { acc += v2; cnt_sim++; }
        if (r > 3 && s3_ > SIM_T) { acc += v3; cnt_sim++; }
    }

    float mean = acc / (float)max(cnt_sim, 1);

    // ---- MLP: h = relu([emb_i, mean] @ W1 + b1); o = h @ W2 + b2 ----
    float h = sb1[lane];
    #pragma unroll
    for (int k = 0; k < 32; k++) {
        float ck = __shfl_sync(FULLMASK, ei, k);
        h = __fmaf_rn(ck, sW1[k * DIM + lane], h);
    }
    #pragma unroll
    for (int k = 0; k < 32; k++) {
        float ck = __shfl_sync(FULLMASK, mean, k);
        h = __fmaf_rn(ck, sW1[(k + 32) * DIM + lane], h);
    }
    h = fmaxf(h, 0.0f);

    float o = sb2[lane];
    #pragma unroll
    for (int k = 0; k < 32; k++) {
        float hk = __shfl_sync(FULLMASK, h, k);
        o = __fmaf_rn(hk, sW2[k * DIM + lane], o);
    }

    if (cnt_nb > 1 && cnt_sim > 0)
        out[gi * DIM + lane] = o;
}

// ---------------------------------------------------------------------------
extern "C" void kernel_launch(void* const* d_in, const int* in_sizes, int n_in,
                              void* d_out, int out_size)
{
    const float* points    = (const float*)d_in[0];
    const float* emb       = (const float*)d_in[1];
    const int*   leaf_mask = (const int*)  d_in[2];
    const float* W1        = (const float*)d_in[3];
    const float* b1        = (const float*)d_in[4];
    const float* W2        = (const float*)d_in[5];
    const float* b2        = (const float*)d_in[6];
    float* out = (float*)d_out;

    prep_kernel<<<(PREP_THR + 255) / 256, 256>>>(points, emb, leaf_mask, out);
    scan_kernel<<<BATCH, 1024>>>();
    scatter_kernel<<<(NP + 255) / 256, 256>>>();

    dim3 grid((NPTS + MWPB - 1) / MWPB, BATCH);
    main_kernel<<<grid, MT>>>(emb, W1, b1, W2, b2, out);
}